// round 3
// baseline (speedup 1.0000x reference)
#include <cuda_runtime.h>

#define NPIXT 262144   // B*H*W = 4*256*256
#define HWSZ  65536    // H*W
#define NCH   32
#define NBLK  1024     // NPIXT / 256
#define TINYF 1.17549435e-38f
#define INFF  __int_as_float(0x7f800000)

// ---------------- scratch (__device__ globals: allocation-free) ----------------
__device__ float g_muN[NPIXT * NCH];   // l2-normalized mu, [N,C]
__device__ float g_w  [NPIXT * NCH];   // weights, [N,C]
__device__ float g_sig[NPIXT * NCH];   // sigma,   [N,C]
__device__ int   g_tblV[8 * NPIXT];    // rank table, valid
__device__ int   g_tblH[8 * NPIXT];    // rank table, hard
__device__ unsigned char g_cls[NPIXT]; // s | valid<<3 | hard<<4
__device__ int   g_bcnt[16 * NBLK];    // per-block counts [(s*2+f)][block]
__device__ int   g_boff[16 * NBLK];    // exclusive prefix
__device__ int   g_count[8];
__device__ int   g_hcount[8];
__device__ float g_protoAcc[768];      // [s][c][3]
__device__ float g_posMW[8 * NCH];     // proto_mu_n * proto_w
__device__ float g_posDen[8 * NCH];    // proto_sigma * proto_w
__device__ float g_simL[8 * 7];        // sim/TEMP logits per (i,k)
__device__ int   g_apix[8 * 256];
__device__ int   g_npix[8 * 256 * 256];
__device__ float g_vnInv;

// ---------------- threefry2x32 (JAX-compatible, partitionable mode) ----------------
__device__ __forceinline__ void tf2x32(unsigned k0, unsigned k1,
                                       unsigned x0, unsigned x1,
                                       unsigned& o0, unsigned& o1) {
    unsigned ks2 = k0 ^ k1 ^ 0x1BD11BDAu;
    x0 += k0; x1 += k1;
#define TF_R(r) { x0 += x1; x1 = __funnelshift_l(x1, x1, (r)); x1 ^= x0; }
    TF_R(13) TF_R(15) TF_R(26) TF_R(6)   x0 += k1;  x1 += ks2 + 1u;
    TF_R(17) TF_R(29) TF_R(16) TF_R(24)  x0 += ks2; x1 += k0  + 2u;
    TF_R(13) TF_R(15) TF_R(26) TF_R(6)   x0 += k0;  x1 += k1  + 3u;
    TF_R(17) TF_R(29) TF_R(16) TF_R(24)  x0 += k1;  x1 += ks2 + 4u;
    TF_R(13) TF_R(15) TF_R(26) TF_R(6)   x0 += ks2; x1 += k0  + 5u;
#undef TF_R
    o0 = x0; o1 = x1;
}

// partitionable-mode 32-bit random bits: xor of both lanes, counts=(hi,lo)=(0,idx)
__device__ __forceinline__ unsigned rbits(unsigned k0, unsigned k1, unsigned idx) {
    unsigned a, b;
    tf2x32(k0, k1, 0u, idx, a, b);
    return a ^ b;
}
__device__ __forceinline__ float u01(unsigned bits) {
    return __uint_as_float((bits >> 9) | 0x3F800000u) - 1.0f;
}

// ---------------- kernel A: classify + per-block counts (+zero protoAcc) ----------------
__global__ void k_classify(const float* __restrict__ label,
                           const float* __restrict__ mask,
                           const float* __restrict__ prob) {
    if (blockIdx.x == 0) {
        for (int idx = threadIdx.x; idx < 768; idx += 256) g_protoAcc[idx] = 0.f;
    }
    int n = blockIdx.x * 256 + threadIdx.x;
    int b = n >> 16, x = n & 65535;
    float mk = mask[b * HWSZ + x];
    int s = 0;
#pragma unroll
    for (int k = 0; k < 8; k++) {
        float lv = label[(b * 8 + k) * HWSZ + x];
        if (lv > 0.5f) s = k;
    }
    bool valid = mk > 0.0f;
    float pv = prob[(b * 8 + s) * HWSZ + x];
    bool hard = valid && (pv < 0.97f);
    g_cls[n] = (unsigned char)(s | (valid ? 8 : 0) | (hard ? 16 : 0));

    __shared__ int cnt[16];
    if (threadIdx.x < 16) cnt[threadIdx.x] = 0;
    __syncthreads();
    if (valid) {
        atomicAdd(&cnt[s * 2 + 0], 1);
        if (hard) atomicAdd(&cnt[s * 2 + 1], 1);
    }
    __syncthreads();
    if (threadIdx.x < 16) g_bcnt[threadIdx.x * NBLK + blockIdx.x] = cnt[threadIdx.x];
}

// ---------------- kernel B: prefix scan of block counts (16 sequences) ----------------
__global__ void k_scan() {
    __shared__ int sm[NBLK];
    int t = threadIdx.x, seq = blockIdx.x;
    int v = g_bcnt[seq * NBLK + t];
    sm[t] = v;
    __syncthreads();
    for (int d = 1; d < NBLK; d <<= 1) {
        int add = (t >= d) ? sm[t - d] : 0;
        __syncthreads();
        sm[t] += add;
        __syncthreads();
    }
    g_boff[seq * NBLK + t] = sm[t] - v;  // exclusive prefix
    if (t == NBLK - 1) {
        int s = seq >> 1;
        if ((seq & 1) == 0) g_count[s] = sm[NBLK - 1];
        else                g_hcount[s] = sm[NBLK - 1];
    }
}

// ---------------- kernel C: scatter rank tables (stable order) ----------------
__global__ void k_scatter() {
    int n = blockIdx.x * 256 + threadIdx.x;
    int code = g_cls[n];
    int s = code & 7;
    bool valid = (code & 8) != 0, hard = (code & 16) != 0;
    __shared__ int wsum[8][8][2];  // [warp][class][flag]
    int warp = threadIdx.x >> 5, lane = threadIdx.x & 31;
    unsigned lmlt = (1u << lane) - 1u;
    int prefv = 0, prefh = 0;
#pragma unroll
    for (int k = 0; k < 8; k++) {
        unsigned mv = __ballot_sync(0xffffffffu, valid && (s == k));
        unsigned mh = __ballot_sync(0xffffffffu, hard && (s == k));
        if (s == k) { prefv = __popc(mv & lmlt); prefh = __popc(mh & lmlt); }
        if (lane == 0) { wsum[warp][k][0] = __popc(mv); wsum[warp][k][1] = __popc(mh); }
    }
    __syncthreads();
    int bofv = 0, bofh = 0;
    for (int w2 = 0; w2 < warp; w2++) { bofv += wsum[w2][s][0]; bofh += wsum[w2][s][1]; }
    if (valid) {
        int r = g_boff[(s * 2 + 0) * NBLK + blockIdx.x] + bofv + prefv;
        g_tblV[s * NPIXT + r] = n;
        if (hard) {
            int rh = g_boff[(s * 2 + 1) * NBLK + blockIdx.x] + bofh + prefh;
            g_tblH[s * NPIXT + rh] = n;
        }
    }
}

// ---------------- kernel D: transpose to [N,C] (+normalize mu) + prototype sums ----------------
__global__ void k_transpose(const float* __restrict__ w_in,
                            const float* __restrict__ mu_in,
                            const float* __restrict__ sg_in) {
    __shared__ float acc[768];
    for (int idx = threadIdx.x; idx < 768; idx += 256) acc[idx] = 0.f;
    __syncthreads();
    int n = blockIdx.x * 256 + threadIdx.x;
    int b = n >> 16, x = n & 65535;
    int code = g_cls[n];
    int s = code & 7;
    bool valid = (code & 8) != 0;
    size_t base = (size_t)b * (NCH * HWSZ) + x;
    float muv[NCH];
    float nr2 = 0.f;
#pragma unroll
    for (int c = 0; c < NCH; c++) {
        float wv = w_in[base + (size_t)c * HWSZ];
        float sv = sg_in[base + (size_t)c * HWSZ];
        float mv = mu_in[base + (size_t)c * HWSZ];
        muv[c] = mv;
        nr2 += mv * mv;
        g_w[(size_t)n * NCH + c] = wv;
        g_sig[(size_t)n * NCH + c] = sv;
        if (valid) {
            float isw = wv / sv;
            atomicAdd(&acc[(s * NCH + c) * 3 + 0], isw);
            atomicAdd(&acc[(s * NCH + c) * 3 + 1], isw * mv);
            atomicAdd(&acc[(s * NCH + c) * 3 + 2], 1.0f / wv);
        }
    }
    float inv = 1.0f / fmaxf(sqrtf(nr2), 1e-12f);
#pragma unroll
    for (int c = 0; c < NCH; c++) g_muN[(size_t)n * NCH + c] = muv[c] * inv;
    __syncthreads();
    for (int idx = threadIdx.x; idx < 768; idx += 256) atomicAdd(&g_protoAcc[idx], acc[idx]);
}

// ---------------- kernel E: finalize prototypes, sim logits, valid_num, zero out ----------------
__global__ void k_finalize(float* out) {
    int t = threadIdx.x;
    int s = t >> 5, c = t & 31;
    float a0 = g_protoAcc[(s * NCH + c) * 3 + 0];
    float a1 = g_protoAcc[(s * NCH + c) * 3 + 1];
    float a2 = g_protoAcc[(s * NCH + c) * 3 + 2];
    float psig = 1.0f / a0;
    float pmu = a1 / a0;
    float pw = 1.0f / a2;
    float nr2 = pmu * pmu;
#pragma unroll
    for (int ofs = 16; ofs; ofs >>= 1) nr2 += __shfl_xor_sync(0xffffffffu, nr2, ofs);
    float inv = 1.0f / fmaxf(sqrtf(nr2), 1e-12f);
    float mun = pmu * inv;
    __shared__ float sMW[8][NCH], sDen[8][NCH];
    float mw = mun * pw, den = psig * pw;
    g_posMW[s * NCH + c] = mw;
    g_posDen[s * NCH + c] = den;
    sMW[s][c] = mw;
    sDen[s][c] = den;
    __syncthreads();
    if (t < 56) {
        int i = t / 7, k = t % 7, o = (i + 1 + k) & 7;
        float sum = 0.f;
        for (int cc = 0; cc < NCH; cc++) {
            float d = sMW[i][cc] - sMW[o][cc];
            float dn = sDen[i][cc] + sDen[o][cc];
            sum += d * d / dn + logf(dn);
        }
        // sim/TEMP = (-0.5*mean)*2 = -sum/32
        g_simL[i * 7 + k] = (g_count[o] > 0) ? (-sum * (1.0f / 32.0f)) : -INFF;
    }
    if (t == 0) {
        int vn = 0;
        for (int ss = 0; ss < 8; ss++) vn += (g_count[ss] > 0) ? 1 : 0;
        g_vnInv = (vn > 0) ? 1.0f / (float)vn : 0.f;
        out[0] = 0.f;
    }
}

// ---------------- kernel F: sampling (anchors + negatives), JAX RNG exact ----------------
__global__ void k_sample() {
    int i = blockIdx.x, q = blockIdx.y, t = threadIdx.x;
    unsigned ka, kb;
    tf2x32(0u, 42u, 0u, (unsigned)i, ka, kb);  // keys[i] = split(key(42),8)[i]
    if (t == 0) {
        unsigned k1a, k1b;
        tf2x32(ka, kb, 0u, 0u, k1a, k1b);  // k1
        float u = u01(rbits(k1a, k1b, (unsigned)q));
        int hc = g_hcount[i];
        int r = (int)(u * (float)hc);
        int cl = hc - 1; if (cl < 0) cl = 0;
        if (r > cl) r = cl;
        if (r < 0) r = 0;
        int ap = (hc > 0) ? g_tblH[i * NPIXT + r] : 0;
        if (ap < 0) ap = 0;
        if (ap >= NPIXT) ap = NPIXT - 1;
        g_apix[i * 256 + q] = ap;
    }
    unsigned k2a, k2b, k3a, k3b;
    tf2x32(ka, kb, 0u, 1u, k2a, k2b);  // k2
    tf2x32(ka, kb, 0u, 2u, k3a, k3b);  // k3
    unsigned j = (unsigned)(q * 256 + t);
    unsigned b7 = j * 7u;
    float best = -INFF;
    int bi = 0;
#pragma unroll
    for (int k = 0; k < 7; k++) {
        float u = u01(rbits(k2a, k2b, b7 + k));
        u = fmaxf(u + TINYF, TINYF);
        float g = -logf(-logf(u));
        float v = g + g_simL[i * 7 + k];
        if (v > best) { best = v; bi = k; }
    }
    int cls = (i + 1 + bi) & 7;
    int cnt = g_count[cls];
    float u3 = u01(rbits(k3a, k3b, j));
    int r = (int)(u3 * (float)cnt);
    int cl = cnt - 1; if (cl < 0) cl = 0;
    if (r > cl) r = cl;
    if (r < 0) r = 0;
    int p = g_tblV[cls * NPIXT + r];
    if (p < 0) p = 0;
    if (p >= NPIXT) p = NPIXT - 1;
    g_npix[(i * 256 + q) * 256 + t] = p;
}

// ---------------- kernel G: logits + logsumexp + CE accumulation ----------------
__device__ __forceinline__ float cand_logit(int i, int q, int j,
                                            const float* aMW, const float* aDen) {
    float sum = 0.f;
    if (j == 0) {
#pragma unroll
        for (int c = 0; c < NCH; c++) {
            float bmw = g_posMW[i * NCH + c], bden = g_posDen[i * NCH + c];
            float d = aMW[c] - bmw;
            float den = aDen[c] + bden;
            sum += d * d / den + logf(den);
        }
    } else {
        int p = g_npix[(i * 256 + q) * 256 + (j - 1)];
        const float4* m4 = (const float4*)(g_muN + (size_t)p * NCH);
        const float4* w4 = (const float4*)(g_w + (size_t)p * NCH);
        const float4* s4 = (const float4*)(g_sig + (size_t)p * NCH);
#pragma unroll
        for (int c4 = 0; c4 < 8; c4++) {
            float4 m = m4[c4], w = w4[c4], sg = s4[c4];
            {
                float bmw = m.x * w.x, bden = sg.x * w.x;
                float d = aMW[c4 * 4 + 0] - bmw;
                float den = aDen[c4 * 4 + 0] + bden;
                sum += d * d / den + logf(den);
            }
            {
                float bmw = m.y * w.y, bden = sg.y * w.y;
                float d = aMW[c4 * 4 + 1] - bmw;
                float den = aDen[c4 * 4 + 1] + bden;
                sum += d * d / den + logf(den);
            }
            {
                float bmw = m.z * w.z, bden = sg.z * w.z;
                float d = aMW[c4 * 4 + 2] - bmw;
                float den = aDen[c4 * 4 + 2] + bden;
                sum += d * d / den + logf(den);
            }
            {
                float bmw = m.w * w.w, bden = sg.w * w.w;
                float d = aMW[c4 * 4 + 3] - bmw;
                float den = aDen[c4 * 4 + 3] + bden;
                sum += d * d / den + logf(den);
            }
        }
    }
    // logit = _mls/TEMP = (-0.5*mean)/0.5 = -sum/32
    return -sum * (1.0f / 32.0f);
}

__global__ void k_logits(float* out) {
    int i = blockIdx.x, q = blockIdx.y, t = threadIdx.x;
    __shared__ float aMW[NCH], aDen[NCH];
    __shared__ float red[256];
    int ap = g_apix[i * 256 + q];
    if (t < NCH) {
        float m = g_muN[(size_t)ap * NCH + t];
        float w = g_w[(size_t)ap * NCH + t];
        float sg = g_sig[(size_t)ap * NCH + t];
        aMW[t] = m * w;   // anchor normalized mu * weight
        aDen[t] = sg * w; // anchor sigma * weight
    }
    __syncthreads();
    float lg0 = cand_logit(i, q, t, aMW, aDen);
    float lg1 = (t == 0) ? cand_logit(i, q, 256, aMW, aDen) : -INFF;

    // block max
    float mymax = fmaxf(lg0, lg1);
    red[t] = mymax;
    __syncthreads();
    for (int ofs = 128; ofs; ofs >>= 1) {
        if (t < ofs) red[t] = fmaxf(red[t], red[t + ofs]);
        __syncthreads();
    }
    float M = red[0];
    __syncthreads();
    float ex = expf(lg0 - M) + ((t == 0) ? expf(lg1 - M) : 0.f);
    red[t] = ex;
    __syncthreads();
    for (int ofs = 128; ofs; ofs >>= 1) {
        if (t < ofs) red[t] += red[t + ofs];
        __syncthreads();
    }
    if (t == 0) {
        float lse = M + logf(red[0]);
        bool ok = (g_hcount[i] > 0) && (g_count[i] > 0);
        if (ok) atomicAdd(out, (lse - lg0) * g_vnInv * (1.0f / 256.0f));
    }
}

// ---------------- launch ----------------
extern "C" void kernel_launch(void* const* d_in, const int* in_sizes, int n_in,
                              void* d_out, int out_size) {
    const float* weights = (const float*)d_in[0];
    const float* mu      = (const float*)d_in[1];
    const float* sigma   = (const float*)d_in[2];
    const float* label   = (const float*)d_in[3];
    const float* mask    = (const float*)d_in[4];
    const float* prob    = (const float*)d_in[5];
    float* out = (float*)d_out;

    k_classify<<<NBLK, 256>>>(label, mask, prob);
    k_scan<<<16, NBLK>>>();
    k_scatter<<<NBLK, 256>>>();
    k_transpose<<<NBLK, 256>>>(weights, mu, sigma);
    k_finalize<<<1, 256>>>(out);
    k_sample<<<dim3(8, 256), 256>>>();
    k_logits<<<dim3(8, 256), 256>>>(out);
}

// round 5
// speedup vs baseline: 2.3910x; 2.3910x over previous
#include <cuda_runtime.h>

#define NPIXT 262144   // B*H*W = 4*256*256
#define HWSZ  65536    // H*W
#define NCH   32
#define NBLK  1024     // NPIXT / 256
#define TINYF 1.17549435e-38f
#define INFF  __int_as_float(0x7f800000)

// ---------------- scratch (__device__ globals: allocation-free) ----------------
__device__ float g_muN[NPIXT * NCH];   // l2-normalized mu, [N,C]
__device__ float g_w  [NPIXT * NCH];   // weights, [N,C]
__device__ float g_sig[NPIXT * NCH];   // sigma,   [N,C]
__device__ int   g_tblV[8 * NPIXT];    // rank table, valid
__device__ int   g_tblH[8 * NPIXT];    // rank table, hard
__device__ unsigned char g_cls[NPIXT]; // s | valid<<3 | hard<<4
__device__ int   g_bcnt[16 * NBLK];    // per-block counts [(s*2+f)][block]
__device__ int   g_boff[16 * NBLK];    // exclusive prefix
__device__ int   g_count[8];
__device__ int   g_hcount[8];
__device__ float g_protoAcc[768];      // [k][s][c]  (k: 0=isw,1=isw*mu,2=1/w)
__device__ float g_posMW[8 * NCH];     // proto_mu_n * proto_w
__device__ float g_posDen[8 * NCH];    // proto_sigma * proto_w
__device__ float g_simL[8 * 7];        // sim/TEMP logits per (i,k)
__device__ int   g_apix[8 * 256];
__device__ int   g_npix[8 * 256 * 256];
__device__ float g_vnInv;

// ---------------- threefry2x32 (JAX-compatible, partitionable mode) ----------------
__device__ __forceinline__ void tf2x32(unsigned k0, unsigned k1,
                                       unsigned x0, unsigned x1,
                                       unsigned& o0, unsigned& o1) {
    unsigned ks2 = k0 ^ k1 ^ 0x1BD11BDAu;
    x0 += k0; x1 += k1;
#define TF_R(r) { x0 += x1; x1 = __funnelshift_l(x1, x1, (r)); x1 ^= x0; }
    TF_R(13) TF_R(15) TF_R(26) TF_R(6)   x0 += k1;  x1 += ks2 + 1u;
    TF_R(17) TF_R(29) TF_R(16) TF_R(24)  x0 += ks2; x1 += k0  + 2u;
    TF_R(13) TF_R(15) TF_R(26) TF_R(6)   x0 += k0;  x1 += k1  + 3u;
    TF_R(17) TF_R(29) TF_R(16) TF_R(24)  x0 += k1;  x1 += ks2 + 4u;
    TF_R(13) TF_R(15) TF_R(26) TF_R(6)   x0 += ks2; x1 += k0  + 5u;
#undef TF_R
    o0 = x0; o1 = x1;
}

__device__ __forceinline__ unsigned rbits(unsigned k0, unsigned k1, unsigned idx) {
    unsigned a, b;
    tf2x32(k0, k1, 0u, idx, a, b);
    return a ^ b;
}
__device__ __forceinline__ float u01(unsigned bits) {
    return __uint_as_float((bits >> 9) | 0x3F800000u) - 1.0f;
}

// ---------------- kernel A: classify + per-block counts (+zero protoAcc) ----------------
__global__ void k_classify(const float* __restrict__ label,
                           const float* __restrict__ mask,
                           const float* __restrict__ prob) {
    if (blockIdx.x == 0) {
        for (int idx = threadIdx.x; idx < 768; idx += 256) g_protoAcc[idx] = 0.f;
    }
    int n = blockIdx.x * 256 + threadIdx.x;
    int b = n >> 16, x = n & 65535;
    float mk = mask[b * HWSZ + x];
    int s = 0;
#pragma unroll
    for (int k = 0; k < 8; k++) {
        float lv = label[(b * 8 + k) * HWSZ + x];
        if (lv > 0.5f) s = k;
    }
    bool valid = mk > 0.0f;
    float pv = prob[(b * 8 + s) * HWSZ + x];
    bool hard = valid && (pv < 0.97f);
    g_cls[n] = (unsigned char)(s | (valid ? 8 : 0) | (hard ? 16 : 0));

    __shared__ int cnt[16];
    if (threadIdx.x < 16) cnt[threadIdx.x] = 0;
    __syncthreads();
    if (valid) {
        atomicAdd(&cnt[s * 2 + 0], 1);
        if (hard) atomicAdd(&cnt[s * 2 + 1], 1);
    }
    __syncthreads();
    if (threadIdx.x < 16) g_bcnt[threadIdx.x * NBLK + blockIdx.x] = cnt[threadIdx.x];
}

// ---------------- kernel B: prefix scan of block counts (16 sequences) ----------------
__global__ void k_scan() {
    __shared__ int sm[NBLK];
    int t = threadIdx.x, seq = blockIdx.x;
    int v = g_bcnt[seq * NBLK + t];
    sm[t] = v;
    __syncthreads();
    for (int d = 1; d < NBLK; d <<= 1) {
        int add = (t >= d) ? sm[t - d] : 0;
        __syncthreads();
        sm[t] += add;
        __syncthreads();
    }
    g_boff[seq * NBLK + t] = sm[t] - v;  // exclusive prefix
    if (t == NBLK - 1) {
        int s = seq >> 1;
        if ((seq & 1) == 0) g_count[s] = sm[NBLK - 1];
        else                g_hcount[s] = sm[NBLK - 1];
    }
}

// ---------------- kernel C: scatter rank tables (stable order) ----------------
__global__ void k_scatter() {
    int n = blockIdx.x * 256 + threadIdx.x;
    int code = g_cls[n];
    int s = code & 7;
    bool valid = (code & 8) != 0, hard = (code & 16) != 0;
    __shared__ int wsum[8][8][2];  // [warp][class][flag]
    int warp = threadIdx.x >> 5, lane = threadIdx.x & 31;
    unsigned lmlt = (1u << lane) - 1u;
    int prefv = 0, prefh = 0;
#pragma unroll
    for (int k = 0; k < 8; k++) {
        unsigned mv = __ballot_sync(0xffffffffu, valid && (s == k));
        unsigned mh = __ballot_sync(0xffffffffu, hard && (s == k));
        if (s == k) { prefv = __popc(mv & lmlt); prefh = __popc(mh & lmlt); }
        if (lane == 0) { wsum[warp][k][0] = __popc(mv); wsum[warp][k][1] = __popc(mh); }
    }
    __syncthreads();
    int bofv = 0, bofh = 0;
    for (int w2 = 0; w2 < warp; w2++) { bofv += wsum[w2][s][0]; bofh += wsum[w2][s][1]; }
    if (valid) {
        int r = g_boff[(s * 2 + 0) * NBLK + blockIdx.x] + bofv + prefv;
        g_tblV[s * NPIXT + r] = n;
        if (hard) {
            int rh = g_boff[(s * 2 + 1) * NBLK + blockIdx.x] + bofh + prefh;
            g_tblH[s * NPIXT + rh] = n;
        }
    }
}

// ---------------- kernel D: staged tiled transpose + mu-normalize + prototype sums ----
// Block = 256 threads (8 warps), handles 256 pixels in 8 stages of 32 pixels.
// Phase 1 (per stage): coalesced channel-major reads -> padded smem tiles.
// Phase 2 (per stage): lane==channel; coalesced [N,C] writes; shfl-allreduce for
//   the mu norm; per-warp NON-atomic smem accumulators for prototype sums.
__global__ void __launch_bounds__(256) k_transpose(const float* __restrict__ w_in,
                                                   const float* __restrict__ mu_in,
                                                   const float* __restrict__ sg_in) {
    __shared__ float tw[32][33], tm[32][33], ts[32][33];
    __shared__ float acc[8][768];    // [warp][k*256 + s*32 + c]
    int t = threadIdx.x, warp = t >> 5, lane = t & 31;
    for (int j = t; j < 8 * 768; j += 256) ((float*)acc)[j] = 0.f;

    int blockPix = blockIdx.x * 256;
    int b = blockPix >> 16;                 // 65536 % 256 == 0: block stays in one b
    size_t base = (size_t)b * (NCH * HWSZ) + (blockPix & 65535);

#pragma unroll 1
    for (int st = 0; st < 8; st++) {
        int pixOfs = st * 32;
        __syncthreads();
        // ---- phase 1: coalesced loads into tiles ----
#pragma unroll
        for (int i = 0; i < 4; i++) {
            int c = warp + i * 8;
            size_t a = base + (size_t)c * HWSZ + pixOfs + lane;
            tw[lane][c] = w_in[a];
            tm[lane][c] = mu_in[a];
            ts[lane][c] = sg_in[a];
        }
        __syncthreads();
        // ---- phase 2: 4 pixels per warp, lane = channel ----
#pragma unroll
        for (int j = 0; j < 4; j++) {
            int p = warp * 4 + j;
            int n = blockPix + pixOfs + p;
            float wv = tw[p][lane];
            float mv = tm[p][lane];
            float sv = ts[p][lane];
            float nr2 = mv * mv;
#pragma unroll
            for (int ofs = 16; ofs; ofs >>= 1) nr2 += __shfl_xor_sync(0xffffffffu, nr2, ofs);
            float inv = 1.0f / fmaxf(sqrtf(nr2), 1e-12f);
            size_t o = (size_t)n * NCH + lane;
            g_w[o] = wv;
            g_sig[o] = sv;
            g_muN[o] = mv * inv;
            int code = g_cls[n];
            if (code & 8) {
                int s = code & 7;
                float isw = wv / sv;
                acc[warp][0 * 256 + s * 32 + lane] += isw;
                acc[warp][1 * 256 + s * 32 + lane] += isw * mv;
                acc[warp][2 * 256 + s * 32 + lane] += 1.0f / wv;
            }
        }
    }
    __syncthreads();
    // ---- block reduce over warps + global red-add ----
#pragma unroll
    for (int j = 0; j < 3; j++) {
        int idx = t + j * 256;
        float sum = 0.f;
#pragma unroll
        for (int w2 = 0; w2 < 8; w2++) sum += acc[w2][idx];
        if (sum != 0.f) atomicAdd(&g_protoAcc[idx], sum);
    }
}

// ---------------- kernel E: finalize prototypes, sim logits, valid_num, zero out ------
__global__ void k_finalize(float* out) {
    int t = threadIdx.x;
    int s = t >> 5, c = t & 31;
    float a0 = g_protoAcc[0 * 256 + s * 32 + c];
    float a1 = g_protoAcc[1 * 256 + s * 32 + c];
    float a2 = g_protoAcc[2 * 256 + s * 32 + c];
    float psig = 1.0f / a0;
    float pmu = a1 / a0;
    float pw = 1.0f / a2;
    float nr2 = pmu * pmu;
#pragma unroll
    for (int ofs = 16; ofs; ofs >>= 1) nr2 += __shfl_xor_sync(0xffffffffu, nr2, ofs);
    float inv = 1.0f / fmaxf(sqrtf(nr2), 1e-12f);
    float mun = pmu * inv;
    __shared__ float sMW[8][NCH], sDen[8][NCH];
    float mw = mun * pw, den = psig * pw;
    g_posMW[s * NCH + c] = mw;
    g_posDen[s * NCH + c] = den;
    sMW[s][c] = mw;
    sDen[s][c] = den;
    __syncthreads();
    if (t < 56) {
        int i = t / 7, k = t % 7, o = (i + 1 + k) & 7;
        float sum = 0.f;
        for (int cc = 0; cc < NCH; cc++) {
            float d = sMW[i][cc] - sMW[o][cc];
            float dn = sDen[i][cc] + sDen[o][cc];
            sum += d * d / dn + logf(dn);
        }
        // sim/TEMP = (-0.5*mean)*2 = -sum/32
        g_simL[i * 7 + k] = (g_count[o] > 0) ? (-sum * (1.0f / 32.0f)) : -INFF;
    }
    if (t == 0) {
        int vn = 0;
        for (int ss = 0; ss < 8; ss++) vn += (g_count[ss] > 0) ? 1 : 0;
        g_vnInv = (vn > 0) ? 1.0f / (float)vn : 0.f;
        out[0] = 0.f;
    }
}

// ---------------- kernel F: sampling (anchors + negatives), JAX RNG exact -------------
__global__ void k_sample() {
    int i = blockIdx.x, q = blockIdx.y, t = threadIdx.x;
    unsigned ka, kb;
    tf2x32(0u, 42u, 0u, (unsigned)i, ka, kb);  // keys[i] = split(key(42),8)[i]
    if (t == 0) {
        unsigned k1a, k1b;
        tf2x32(ka, kb, 0u, 0u, k1a, k1b);  // k1
        float u = u01(rbits(k1a, k1b, (unsigned)q));
        int hc = g_hcount[i];
        int r = (int)(u * (float)hc);
        int cl = hc - 1; if (cl < 0) cl = 0;
        if (r > cl) r = cl;
        if (r < 0) r = 0;
        int ap = (hc > 0) ? g_tblH[i * NPIXT + r] : 0;
        if (ap < 0) ap = 0;
        if (ap >= NPIXT) ap = NPIXT - 1;
        g_apix[i * 256 + q] = ap;
    }
    unsigned k2a, k2b, k3a, k3b;
    tf2x32(ka, kb, 0u, 1u, k2a, k2b);  // k2
    tf2x32(ka, kb, 0u, 2u, k3a, k3b);  // k3
    unsigned j = (unsigned)(q * 256 + t);
    unsigned b7 = j * 7u;
    float best = -INFF;
    int bi = 0;
#pragma unroll
    for (int k = 0; k < 7; k++) {
        float u = u01(rbits(k2a, k2b, b7 + k));
        u = fmaxf(u + TINYF, TINYF);
        float g = -logf(-logf(u));
        float v = g + g_simL[i * 7 + k];
        if (v > best) { best = v; bi = k; }
    }
    int cls = (i + 1 + bi) & 7;
    int cnt = g_count[cls];
    float u3 = u01(rbits(k3a, k3b, j));
    int r = (int)(u3 * (float)cnt);
    int cl = cnt - 1; if (cl < 0) cl = 0;
    if (r > cl) r = cl;
    if (r < 0) r = 0;
    int p = g_tblV[cls * NPIXT + r];
    if (p < 0) p = 0;
    if (p >= NPIXT) p = NPIXT - 1;
    g_npix[(i * 256 + q) * 256 + t] = p;
}

// ---------------- kernel G: logits + logsumexp + CE accumulation ----------------------
__device__ __forceinline__ float cand_logit(int i, int q, int j,
                                            const float* aMW, const float* aDen) {
    float sum = 0.f;
    if (j == 0) {
#pragma unroll
        for (int c = 0; c < NCH; c++) {
            float bmw = g_posMW[i * NCH + c], bden = g_posDen[i * NCH + c];
            float d = aMW[c] - bmw;
            float den = aDen[c] + bden;
            sum += d * d / den + logf(den);
        }
    } else {
        int p = g_npix[(i * 256 + q) * 256 + (j - 1)];
        const float4* m4 = (const float4*)(g_muN + (size_t)p * NCH);
        const float4* w4 = (const float4*)(g_w + (size_t)p * NCH);
        const float4* s4 = (const float4*)(g_sig + (size_t)p * NCH);
#pragma unroll
        for (int c4 = 0; c4 < 8; c4++) {
            float4 m = m4[c4], w = w4[c4], sg = s4[c4];
            {
                float bmw = m.x * w.x, bden = sg.x * w.x;
                float d = aMW[c4 * 4 + 0] - bmw;
                float den = aDen[c4 * 4 + 0] + bden;
                sum += d * d / den + logf(den);
            }
            {
                float bmw = m.y * w.y, bden = sg.y * w.y;
                float d = aMW[c4 * 4 + 1] - bmw;
                float den = aDen[c4 * 4 + 1] + bden;
                sum += d * d / den + logf(den);
            }
            {
                float bmw = m.z * w.z, bden = sg.z * w.z;
                float d = aMW[c4 * 4 + 2] - bmw;
                float den = aDen[c4 * 4 + 2] + bden;
                sum += d * d / den + logf(den);
            }
            {
                float bmw = m.w * w.w, bden = sg.w * w.w;
                float d = aMW[c4 * 4 + 3] - bmw;
                float den = aDen[c4 * 4 + 3] + bden;
                sum += d * d / den + logf(den);
            }
        }
    }
    // logit = _mls/TEMP = (-0.5*mean)/0.5 = -sum/32
    return -sum * (1.0f / 32.0f);
}

__global__ void k_logits(float* out) {
    int i = blockIdx.x, q = blockIdx.y, t = threadIdx.x;
    __shared__ float aMW[NCH], aDen[NCH];
    __shared__ float red[256];
    int ap = g_apix[i * 256 + q];
    if (t < NCH) {
        float m = g_muN[(size_t)ap * NCH + t];
        float w = g_w[(size_t)ap * NCH + t];
        float sg = g_sig[(size_t)ap * NCH + t];
        aMW[t] = m * w;   // anchor normalized mu * weight
        aDen[t] = sg * w; // anchor sigma * weight
    }
    __syncthreads();
    float lg0 = cand_logit(i, q, t, aMW, aDen);
    float lg1 = (t == 0) ? cand_logit(i, q, 256, aMW, aDen) : -INFF;

    float mymax = fmaxf(lg0, lg1);
    red[t] = mymax;
    __syncthreads();
    for (int ofs = 128; ofs; ofs >>= 1) {
        if (t < ofs) red[t] = fmaxf(red[t], red[t + ofs]);
        __syncthreads();
    }
    float M = red[0];
    __syncthreads();
    float ex = expf(lg0 - M) + ((t == 0) ? expf(lg1 - M) : 0.f);
    red[t] = ex;
    __syncthreads();
    for (int ofs = 128; ofs; ofs >>= 1) {
        if (t < ofs) red[t] += red[t + ofs];
        __syncthreads();
    }
    if (t == 0) {
        float lse = M + logf(red[0]);
        bool ok = (g_hcount[i] > 0) && (g_count[i] > 0);
        if (ok) atomicAdd(out, (lse - lg0) * g_vnInv * (1.0f / 256.0f));
    }
}

// ---------------- launch ----------------
extern "C" void kernel_launch(void* const* d_in, const int* in_sizes, int n_in,
                              void* d_out, int out_size) {
    const float* weights = (const float*)d_in[0];
    const float* mu      = (const float*)d_in[1];
    const float* sigma   = (const float*)d_in[2];
    const float* label   = (const float*)d_in[3];
    const float* mask    = (const float*)d_in[4];
    const float* prob    = (const float*)d_in[5];
    float* out = (float*)d_out;

    k_classify<<<NBLK, 256>>>(label, mask, prob);
    k_scan<<<16, NBLK>>>();
    k_scatter<<<NBLK, 256>>>();
    k_transpose<<<NBLK, 256>>>(weights, mu, sigma);
    k_finalize<<<1, 256>>>(out);
    k_sample<<<dim3(8, 256), 256>>>();
    k_logits<<<dim3(8, 256), 256>>>(out);
}

// round 7
// speedup vs baseline: 3.8555x; 1.6125x over previous
#include <cuda_runtime.h>

#define NPIXT 262144   // B*H*W = 4*256*256
#define HWSZ  65536    // H*W
#define NCH   32
#define NBLK  1024     // NPIXT / 256
#define TINYF 1.17549435e-38f
#define INFF  __int_as_float(0x7f800000)

// ---------------- scratch (__device__ globals: allocation-free) ----------------
__device__ float g_pk[NPIXT * 64];     // per-pixel [mw[32] | den[32]] (mw = muN*w, den = sig*w)
__device__ int   g_tblV[8 * NPIXT];    // rank table, valid
__device__ int   g_tblH[8 * NPIXT];    // rank table, hard
__device__ unsigned char g_cls[NPIXT]; // s | valid<<3 | hard<<4
__device__ int   g_bcnt[16 * NBLK];    // per-block counts [(s*2+f)][block]
__device__ int   g_boff[16 * NBLK];    // exclusive prefix
__device__ int   g_count[8];
__device__ int   g_hcount[8];
__device__ float g_protoAcc[768];      // [k][s][c]  (k: 0=isw,1=isw*mu,2=1/w)
__device__ float g_posMW[8 * NCH];     // proto_mu_n * proto_w
__device__ float g_posDen[8 * NCH];    // proto_sigma * proto_w
__device__ float g_simL[8 * 7];        // sim/TEMP logits per (i,k)
__device__ float g_vnInv;

// ---------------- threefry2x32 (JAX-compatible, partitionable mode) ----------------
__device__ __forceinline__ void tf2x32(unsigned k0, unsigned k1,
                                       unsigned x0, unsigned x1,
                                       unsigned& o0, unsigned& o1) {
    unsigned ks2 = k0 ^ k1 ^ 0x1BD11BDAu;
    x0 += k0; x1 += k1;
#define TF_R(r) { x0 += x1; x1 = __funnelshift_l(x1, x1, (r)); x1 ^= x0; }
    TF_R(13) TF_R(15) TF_R(26) TF_R(6)   x0 += k1;  x1 += ks2 + 1u;
    TF_R(17) TF_R(29) TF_R(16) TF_R(24)  x0 += ks2; x1 += k0  + 2u;
    TF_R(13) TF_R(15) TF_R(26) TF_R(6)   x0 += k0;  x1 += k1  + 3u;
    TF_R(17) TF_R(29) TF_R(16) TF_R(24)  x0 += k1;  x1 += ks2 + 4u;
    TF_R(13) TF_R(15) TF_R(26) TF_R(6)   x0 += ks2; x1 += k0  + 5u;
#undef TF_R
    o0 = x0; o1 = x1;
}

__device__ __forceinline__ unsigned rbits(unsigned k0, unsigned k1, unsigned idx) {
    unsigned a, b;
    tf2x32(k0, k1, 0u, idx, a, b);
    return a ^ b;
}
__device__ __forceinline__ float u01(unsigned bits) {
    return __uint_as_float((bits >> 9) | 0x3F800000u) - 1.0f;
}

// ---------------- kernel A: classify + per-block counts (+zero protoAcc) ----------------
__global__ void k_classify(const float* __restrict__ label,
                           const float* __restrict__ mask,
                           const float* __restrict__ prob) {
    if (blockIdx.x == 0) {
        for (int idx = threadIdx.x; idx < 768; idx += 256) g_protoAcc[idx] = 0.f;
    }
    int n = blockIdx.x * 256 + threadIdx.x;
    int b = n >> 16, x = n & 65535;
    float mk = mask[b * HWSZ + x];
    int s = 0;
#pragma unroll
    for (int k = 0; k < 8; k++) {
        float lv = label[(b * 8 + k) * HWSZ + x];
        if (lv > 0.5f) s = k;
    }
    bool valid = mk > 0.0f;
    float pv = prob[(b * 8 + s) * HWSZ + x];
    bool hard = valid && (pv < 0.97f);
    g_cls[n] = (unsigned char)(s | (valid ? 8 : 0) | (hard ? 16 : 0));

    __shared__ int cnt[16];
    if (threadIdx.x < 16) cnt[threadIdx.x] = 0;
    __syncthreads();
    if (valid) {
        atomicAdd(&cnt[s * 2 + 0], 1);
        if (hard) atomicAdd(&cnt[s * 2 + 1], 1);
    }
    __syncthreads();
    if (threadIdx.x < 16) g_bcnt[threadIdx.x * NBLK + blockIdx.x] = cnt[threadIdx.x];
}

// ---------------- kernel D: staged tiled transpose + mu-normalize + prototype sums ----
__global__ void __launch_bounds__(256) k_transpose(const float* __restrict__ w_in,
                                                   const float* __restrict__ mu_in,
                                                   const float* __restrict__ sg_in) {
    __shared__ float tw[32][33], tm[32][33], ts[32][33];
    __shared__ float acc[8][768];    // [warp][k*256 + s*32 + c]
    int t = threadIdx.x, warp = t >> 5, lane = t & 31;
    for (int j = t; j < 8 * 768; j += 256) ((float*)acc)[j] = 0.f;

    int blockPix = blockIdx.x * 256;
    int b = blockPix >> 16;                 // 65536 % 256 == 0: block stays in one b
    size_t base = (size_t)b * (NCH * HWSZ) + (blockPix & 65535);

#pragma unroll 1
    for (int st = 0; st < 8; st++) {
        int pixOfs = st * 32;
        __syncthreads();
        // ---- phase 1: coalesced loads into tiles ----
#pragma unroll
        for (int i = 0; i < 4; i++) {
            int c = warp + i * 8;
            size_t a = base + (size_t)c * HWSZ + pixOfs + lane;
            tw[lane][c] = w_in[a];
            tm[lane][c] = mu_in[a];
            ts[lane][c] = sg_in[a];
        }
        __syncthreads();
        // ---- phase 2: 4 pixels per warp, lane = channel ----
#pragma unroll
        for (int j = 0; j < 4; j++) {
            int p = warp * 4 + j;
            int n = blockPix + pixOfs + p;
            float wv = tw[p][lane];
            float mv = tm[p][lane];
            float sv = ts[p][lane];
            float nr2 = mv * mv;
#pragma unroll
            for (int ofs = 16; ofs; ofs >>= 1) nr2 += __shfl_xor_sync(0xffffffffu, nr2, ofs);
            float inv = 1.0f / fmaxf(sqrtf(nr2), 1e-12f);
            size_t o = (size_t)n * 64 + lane;
            g_pk[o]      = (mv * inv) * wv;  // mw
            g_pk[o + 32] = sv * wv;          // den
            int code = g_cls[n];
            if (code & 8) {
                int s = code & 7;
                float isw = wv / sv;
                acc[warp][0 * 256 + s * 32 + lane] += isw;
                acc[warp][1 * 256 + s * 32 + lane] += isw * mv;
                acc[warp][2 * 256 + s * 32 + lane] += 1.0f / wv;
            }
        }
    }
    __syncthreads();
#pragma unroll
    for (int j = 0; j < 3; j++) {
        int idx = t + j * 256;
        float sum = 0.f;
#pragma unroll
        for (int w2 = 0; w2 < 8; w2++) sum += acc[w2][idx];
        if (sum != 0.f) atomicAdd(&g_protoAcc[idx], sum);
    }
}

// ---------------- kernel B: prefix scan of block counts (16 sequences) ----------------
__global__ void k_scan() {
    __shared__ int sm[NBLK];
    int t = threadIdx.x, seq = blockIdx.x;
    int v = g_bcnt[seq * NBLK + t];
    sm[t] = v;
    __syncthreads();
    for (int d = 1; d < NBLK; d <<= 1) {
        int add = (t >= d) ? sm[t - d] : 0;
        __syncthreads();
        sm[t] += add;
        __syncthreads();
    }
    g_boff[seq * NBLK + t] = sm[t] - v;  // exclusive prefix
    if (t == NBLK - 1) {
        int s = seq >> 1;
        if ((seq & 1) == 0) g_count[s] = sm[NBLK - 1];
        else                g_hcount[s] = sm[NBLK - 1];
    }
}

// ---------------- kernel C: scatter rank tables + (block 0) finalize ------------------
__global__ void k_scatter(float* out) {
    int n = blockIdx.x * 256 + threadIdx.x;
    int code = g_cls[n];
    int s = code & 7;
    bool valid = (code & 8) != 0, hard = (code & 16) != 0;
    __shared__ int wsum[8][8][2];  // [warp][class][flag]
    int warp = threadIdx.x >> 5, lane = threadIdx.x & 31;
    unsigned lmlt = (1u << lane) - 1u;
    int prefv = 0, prefh = 0;
#pragma unroll
    for (int k = 0; k < 8; k++) {
        unsigned mv = __ballot_sync(0xffffffffu, valid && (s == k));
        unsigned mh = __ballot_sync(0xffffffffu, hard && (s == k));
        if (s == k) { prefv = __popc(mv & lmlt); prefh = __popc(mh & lmlt); }
        if (lane == 0) { wsum[warp][k][0] = __popc(mv); wsum[warp][k][1] = __popc(mh); }
    }
    __syncthreads();
    int bofv = 0, bofh = 0;
    for (int w2 = 0; w2 < warp; w2++) { bofv += wsum[w2][s][0]; bofh += wsum[w2][s][1]; }
    if (valid) {
        int r = g_boff[(s * 2 + 0) * NBLK + blockIdx.x] + bofv + prefv;
        g_tblV[s * NPIXT + r] = n;
        if (hard) {
            int rh = g_boff[(s * 2 + 1) * NBLK + blockIdx.x] + bofh + prefh;
            g_tblH[s * NPIXT + rh] = n;
        }
    }

    // ---- finalize (block 0 only): prototypes, sim logits, valid_num, zero out ----
    if (blockIdx.x == 0) {
        int t = threadIdx.x;
        int ss = t >> 5, c = t & 31;
        float a0 = g_protoAcc[0 * 256 + ss * 32 + c];
        float a1 = g_protoAcc[1 * 256 + ss * 32 + c];
        float a2 = g_protoAcc[2 * 256 + ss * 32 + c];
        float psig = 1.0f / a0;
        float pmu = a1 / a0;
        float pw = 1.0f / a2;
        float nr2 = pmu * pmu;
#pragma unroll
        for (int ofs = 16; ofs; ofs >>= 1) nr2 += __shfl_xor_sync(0xffffffffu, nr2, ofs);
        float inv = 1.0f / fmaxf(sqrtf(nr2), 1e-12f);
        float mun = pmu * inv;
        __shared__ float sMW[8][NCH], sDen[8][NCH];
        float mw = mun * pw, den = psig * pw;
        g_posMW[ss * NCH + c] = mw;
        g_posDen[ss * NCH + c] = den;
        sMW[ss][c] = mw;
        sDen[ss][c] = den;
        __syncthreads();
        if (t < 56) {
            int i = t / 7, k = t % 7, o = (i + 1 + k) & 7;
            float sum = 0.f;
            for (int cc = 0; cc < NCH; cc++) {
                float d = sMW[i][cc] - sMW[o][cc];
                float dn = sDen[i][cc] + sDen[o][cc];
                sum += d * d / dn + logf(dn);
            }
            g_simL[i * 7 + k] = (g_count[o] > 0) ? (-sum * (1.0f / 32.0f)) : -INFF;
        }
        if (t == 0) {
            int vn = 0;
            for (int s2 = 0; s2 < 8; s2++) vn += (g_count[s2] > 0) ? 1 : 0;
            g_vnInv = (vn > 0) ? 1.0f / (float)vn : 0.f;
            out[0] = 0.f;
        }
    }
}

// ---------------- MLS logit between anchor (smem arrays) and candidate ---------------
__device__ __forceinline__ float mls_logit(const float* __restrict__ aMW,
                                           const float* __restrict__ aDen,
                                           const float* __restrict__ bMW,
                                           const float* __restrict__ bDen) {
    const float4* bm4 = (const float4*)bMW;
    const float4* bd4 = (const float4*)bDen;
    float total = 0.f;
#pragma unroll
    for (int g = 0; g < 4; g++) {
        float4 m0 = bm4[2 * g], m1 = bm4[2 * g + 1];
        float4 d0 = bd4[2 * g], d1 = bd4[2 * g + 1];
        float mw[8] = {m0.x, m0.y, m0.z, m0.w, m1.x, m1.y, m1.z, m1.w};
        float dn[8] = {d0.x, d0.y, d0.z, d0.w, d1.x, d1.y, d1.z, d1.w};
        float prod = 1.f, qs = 0.f;
#pragma unroll
        for (int u = 0; u < 8; u++) {
            int c = g * 8 + u;
            float den = aDen[c] + dn[u];
            float d = aMW[c] - mw[u];
            qs += __fdividef(d * d, den);
            prod *= den;
        }
        total += qs + __logf(prod);
    }
    return -total * (1.0f / 32.0f);  // _mls/TEMP
}

// ---------------- kernel G: fused sampling + logits + logsumexp + CE ------------------
__global__ void __launch_bounds__(256) k_slog(float* out) {
    int i = blockIdx.x, q = blockIdx.y, t = threadIdx.x;
    int warp = t >> 5, lane = t & 31;
    __shared__ unsigned sk[4];           // k2a,k2b,k3a,k3b
    __shared__ int sap;
    __shared__ float ssim[7];
    __shared__ float aMW[NCH], aDen[NCH];
    __shared__ float sred[8];

    if (t < 7) ssim[t] = g_simL[i * 7 + t];
    if (t == 0) {
        unsigned ka, kb;
        tf2x32(0u, 42u, 0u, (unsigned)i, ka, kb);   // keys[i]
        unsigned k1a, k1b;
        tf2x32(ka, kb, 0u, 0u, k1a, k1b);           // k1
        float u = u01(rbits(k1a, k1b, (unsigned)q));
        int hc = g_hcount[i];
        int r = (int)(u * (float)hc);
        int cl = hc - 1; if (cl < 0) cl = 0;
        if (r > cl) r = cl;
        if (r < 0) r = 0;
        int ap = (hc > 0) ? g_tblH[i * NPIXT + r] : 0;
        if (ap < 0) ap = 0;
        if (ap >= NPIXT) ap = NPIXT - 1;
        sap = ap;
        unsigned a, b;
        tf2x32(ka, kb, 0u, 1u, a, b); sk[0] = a; sk[1] = b;   // k2
        tf2x32(ka, kb, 0u, 2u, a, b); sk[2] = a; sk[3] = b;   // k3
    }
    __syncthreads();
    if (t < NCH) {
        int ap = sap;
        aMW[t]  = g_pk[(size_t)ap * 64 + t];
        aDen[t] = g_pk[(size_t)ap * 64 + 32 + t];
    }
    unsigned k2a = sk[0], k2b = sk[1], k3a = sk[2], k3b = sk[3];

    // ---- negative sampling for this thread's candidate (negative index = t) ----
    unsigned j = (unsigned)(q * 256 + t);
    unsigned b7 = j * 7u;
    float best = -INFF;
    int bi = 0;
#pragma unroll
    for (int k = 0; k < 7; k++) {
        float u = u01(rbits(k2a, k2b, b7 + k));
        u = fmaxf(u + TINYF, TINYF);
        float g = -__logf(-__logf(u));
        float v = g + ssim[k];
        if (v > best) { best = v; bi = k; }
    }
    int cls = (i + 1 + bi) & 7;
    int cnt = g_count[cls];
    float u3 = u01(rbits(k3a, k3b, j));
    int r = (int)(u3 * (float)cnt);
    int cl = cnt - 1; if (cl < 0) cl = 0;
    if (r > cl) r = cl;
    if (r < 0) r = 0;
    int p = g_tblV[cls * NPIXT + r];
    if (p < 0) p = 0;
    if (p >= NPIXT) p = NPIXT - 1;
    __syncthreads();   // anchor smem ready

    // ---- logits: lg0 = this thread's NEGATIVE, lg1 (t==0 only) = POSITIVE ----
    float lg0 = mls_logit(aMW, aDen, g_pk + (size_t)p * 64, g_pk + (size_t)p * 64 + 32);
    float lg1 = (t == 0) ? mls_logit(aMW, aDen, g_posMW + i * NCH, g_posDen + i * NCH)
                         : -INFF;

    // ---- block max (warp shfl + 8-way smem) ----
    float mymax = fmaxf(lg0, lg1);
#pragma unroll
    for (int ofs = 16; ofs; ofs >>= 1) mymax = fmaxf(mymax, __shfl_xor_sync(0xffffffffu, mymax, ofs));
    if (lane == 0) sred[warp] = mymax;
    __syncthreads();
    if (t == 0) {
        float m = sred[0];
#pragma unroll
        for (int w2 = 1; w2 < 8; w2++) m = fmaxf(m, sred[w2]);
        sred[0] = m;
    }
    __syncthreads();
    float M = sred[0];
    __syncthreads();   // everyone read M before sred reuse
    float ex = __expf(lg0 - M) + ((t == 0) ? __expf(lg1 - M) : 0.f);
#pragma unroll
    for (int ofs = 16; ofs; ofs >>= 1) ex += __shfl_xor_sync(0xffffffffu, ex, ofs);
    if (lane == 0) sred[warp] = ex;
    __syncthreads();
    if (t == 0) {
        float sum = 0.f;
#pragma unroll
        for (int w2 = 0; w2 < 8; w2++) sum += sred[w2];
        float lse = M + __logf(sum);
        bool ok = (g_hcount[i] > 0) && (g_count[i] > 0);
        // CE term: lse - POSITIVE logit (lg1), not lg0!
        if (ok) atomicAdd(out, (lse - lg1) * g_vnInv * (1.0f / 256.0f));
    }
}

// ---------------- launch ----------------
extern "C" void kernel_launch(void* const* d_in, const int* in_sizes, int n_in,
                              void* d_out, int out_size) {
    const float* weights = (const float*)d_in[0];
    const float* mu      = (const float*)d_in[1];
    const float* sigma   = (const float*)d_in[2];
    const float* label   = (const float*)d_in[3];
    const float* mask    = (const float*)d_in[4];
    const float* prob    = (const float*)d_in[5];
    float* out = (float*)d_out;

    k_classify<<<NBLK, 256>>>(label, mask, prob);
    k_transpose<<<NBLK, 256>>>(weights, mu, sigma);
    k_scan<<<16, NBLK>>>();
    k_scatter<<<NBLK, 256>>>(out);
    k_slog<<<dim3(8, 256), 256>>>(out);
}

// round 8
// speedup vs baseline: 5.2111x; 1.3516x over previous
#include <cuda_runtime.h>
#include <cuda_fp16.h>

#define NPIXT 262144   // B*H*W = 4*256*256
#define HWSZ  65536    // H*W
#define NCH   32
#define NBLK  1024     // NPIXT / 256
#define TINYF 1.17549435e-38f
#define INFF  __int_as_float(0x7f800000)

// ---------------- scratch (__device__ globals: allocation-free, zero-init) -----------
__device__ __half2 g_pk[NPIXT * 32];   // per-pixel, per-channel (mw, den) fp16 pairs
__device__ int   g_tblV[8 * NPIXT];    // rank table, valid
__device__ int   g_tblH[8 * NPIXT];    // rank table, hard
__device__ unsigned char g_cls[NPIXT]; // s | valid<<3 | hard<<4
__device__ int   g_bcnt[16 * NBLK];    // per-block counts [(s*2+f)][block]
__device__ int   g_boff[16 * NBLK];    // exclusive prefix
__device__ int   g_count[8];
__device__ int   g_hcount[8];
__device__ float g_protoAcc[768];      // [k][s][c]; MUST be zero at kernel_launch entry
__device__ float g_posMW[8 * NCH];     // proto_mu_n * proto_w
__device__ float g_posDen[8 * NCH];    // proto_sigma * proto_w
__device__ float g_simL[8 * 7];        // sim/TEMP logits per (i,k)
__device__ float g_vnInv;

// ---------------- threefry2x32 (JAX-compatible, partitionable mode) ----------------
__device__ __forceinline__ void tf2x32(unsigned k0, unsigned k1,
                                       unsigned x0, unsigned x1,
                                       unsigned& o0, unsigned& o1) {
    unsigned ks2 = k0 ^ k1 ^ 0x1BD11BDAu;
    x0 += k0; x1 += k1;
#define TF_R(r) { x0 += x1; x1 = __funnelshift_l(x1, x1, (r)); x1 ^= x0; }
    TF_R(13) TF_R(15) TF_R(26) TF_R(6)   x0 += k1;  x1 += ks2 + 1u;
    TF_R(17) TF_R(29) TF_R(16) TF_R(24)  x0 += ks2; x1 += k0  + 2u;
    TF_R(13) TF_R(15) TF_R(26) TF_R(6)   x0 += k0;  x1 += k1  + 3u;
    TF_R(17) TF_R(29) TF_R(16) TF_R(24)  x0 += k1;  x1 += ks2 + 4u;
    TF_R(13) TF_R(15) TF_R(26) TF_R(6)   x0 += ks2; x1 += k0  + 5u;
#undef TF_R
    o0 = x0; o1 = x1;
}

__device__ __forceinline__ unsigned rbits(unsigned k0, unsigned k1, unsigned idx) {
    unsigned a, b;
    tf2x32(k0, k1, 0u, idx, a, b);
    return a ^ b;
}
__device__ __forceinline__ float u01(unsigned bits) {
    return __uint_as_float((bits >> 9) | 0x3F800000u) - 1.0f;
}

// ---------------- kernel 1: fused classify + transpose + prototype sums --------------
__global__ void __launch_bounds__(256) k_main(const float* __restrict__ w_in,
                                              const float* __restrict__ mu_in,
                                              const float* __restrict__ sg_in,
                                              const float* __restrict__ label,
                                              const float* __restrict__ mask,
                                              const float* __restrict__ prob) {
    __shared__ float tw[32][33], tm[32][33], ts[32][33];
    __shared__ float acc[8][768];          // [warp][k*256 + s*32 + c]
    __shared__ unsigned char codes[256];
    __shared__ int cnt[16];
    int t = threadIdx.x, warp = t >> 5, lane = t & 31;
    for (int j = t; j < 8 * 768; j += 256) ((float*)acc)[j] = 0.f;
    if (t < 16) cnt[t] = 0;

    int blockPix = blockIdx.x * 256;
    int n = blockPix + t;
    int b = n >> 16, x = n & 65535;

    // ---- classify ----
    float mk = mask[b * HWSZ + x];
    int s = 0;
#pragma unroll
    for (int k = 0; k < 8; k++) {
        float lv = label[(b * 8 + k) * HWSZ + x];
        if (lv > 0.5f) s = k;
    }
    bool valid = mk > 0.0f;
    float pv = prob[(b * 8 + s) * HWSZ + x];
    bool hard = valid && (pv < 0.97f);
    unsigned char code = (unsigned char)(s | (valid ? 8 : 0) | (hard ? 16 : 0));
    codes[t] = code;
    g_cls[n] = code;
    __syncthreads();   // covers acc/cnt zero + codes
    if (valid) {
        atomicAdd(&cnt[s * 2 + 0], 1);
        if (hard) atomicAdd(&cnt[s * 2 + 1], 1);
    }

    // ---- staged transpose ----
    size_t base = (size_t)b * (NCH * HWSZ) + (blockPix & 65535);
#pragma unroll 1
    for (int st = 0; st < 8; st++) {
        int pixOfs = st * 32;
        __syncthreads();
#pragma unroll
        for (int i = 0; i < 4; i++) {
            int c = warp + i * 8;
            size_t a = base + (size_t)c * HWSZ + pixOfs + lane;
            tw[lane][c] = w_in[a];
            tm[lane][c] = mu_in[a];
            ts[lane][c] = sg_in[a];
        }
        __syncthreads();
#pragma unroll
        for (int j = 0; j < 4; j++) {
            int p = warp * 4 + j;
            int pin = pixOfs + p;            // pixel index within block
            int np = blockPix + pin;
            float wv = tw[p][lane];
            float mv = tm[p][lane];
            float sv = ts[p][lane];
            float nr2 = mv * mv;
#pragma unroll
            for (int ofs = 16; ofs; ofs >>= 1) nr2 += __shfl_xor_sync(0xffffffffu, nr2, ofs);
            float inv = 1.0f / fmaxf(sqrtf(nr2), 1e-12f);
            g_pk[(size_t)np * 32 + lane] = __floats2half2_rn((mv * inv) * wv, sv * wv);
            int pc = codes[pin];
            if (pc & 8) {
                int ps = pc & 7;
                float isw = __fdividef(wv, sv);
                acc[warp][0 * 256 + ps * 32 + lane] += isw;
                acc[warp][1 * 256 + ps * 32 + lane] += isw * mv;
                acc[warp][2 * 256 + ps * 32 + lane] += __frcp_rn(wv);
            }
        }
    }
    __syncthreads();
    if (t < 16) g_bcnt[t * NBLK + blockIdx.x] = cnt[t];
#pragma unroll
    for (int j = 0; j < 3; j++) {
        int idx = t + j * 256;
        float sum = 0.f;
#pragma unroll
        for (int w2 = 0; w2 < 8; w2++) sum += acc[w2][idx];
        if (sum != 0.f) atomicAdd(&g_protoAcc[idx], sum);
    }
}

// ---------------- kernel 2: warp-shfl prefix scan of block counts --------------------
__global__ void k_scan() {
    __shared__ int ws[32];
    int t = threadIdx.x, seq = blockIdx.x, warp = t >> 5, lane = t & 31;
    int v = g_bcnt[seq * NBLK + t];
    int x = v;
#pragma unroll
    for (int d = 1; d < 32; d <<= 1) {
        int y = __shfl_up_sync(0xffffffffu, x, d);
        if (lane >= d) x += y;
    }
    if (lane == 31) ws[warp] = x;
    __syncthreads();
    if (warp == 0) {
        int y = ws[lane];
#pragma unroll
        for (int d = 1; d < 32; d <<= 1) {
            int z = __shfl_up_sync(0xffffffffu, y, d);
            if (lane >= d) y += z;
        }
        ws[lane] = y;
    }
    __syncthreads();
    int incl = x + (warp ? ws[warp - 1] : 0);
    g_boff[seq * NBLK + t] = incl - v;
    if (t == NBLK - 1) {
        int s = seq >> 1;
        if ((seq & 1) == 0) g_count[s] = incl;
        else                g_hcount[s] = incl;
    }
}

// ---------------- kernel 3: scatter rank tables + (block 0) finalize -----------------
__global__ void k_scatter(float* out) {
    int n = blockIdx.x * 256 + threadIdx.x;
    int code = g_cls[n];
    int s = code & 7;
    bool valid = (code & 8) != 0, hard = (code & 16) != 0;
    __shared__ int wsum[8][8][2];  // [warp][class][flag]
    int warp = threadIdx.x >> 5, lane = threadIdx.x & 31;
    unsigned lmlt = (1u << lane) - 1u;
    int prefv = 0, prefh = 0;
#pragma unroll
    for (int k = 0; k < 8; k++) {
        unsigned mv = __ballot_sync(0xffffffffu, valid && (s == k));
        unsigned mh = __ballot_sync(0xffffffffu, hard && (s == k));
        if (s == k) { prefv = __popc(mv & lmlt); prefh = __popc(mh & lmlt); }
        if (lane == 0) { wsum[warp][k][0] = __popc(mv); wsum[warp][k][1] = __popc(mh); }
    }
    __syncthreads();
    int bofv = 0, bofh = 0;
    for (int w2 = 0; w2 < warp; w2++) { bofv += wsum[w2][s][0]; bofh += wsum[w2][s][1]; }
    if (valid) {
        int r = g_boff[(s * 2 + 0) * NBLK + blockIdx.x] + bofv + prefv;
        g_tblV[s * NPIXT + r] = n;
        if (hard) {
            int rh = g_boff[(s * 2 + 1) * NBLK + blockIdx.x] + bofh + prefh;
            g_tblH[s * NPIXT + rh] = n;
        }
    }

    // ---- finalize (block 0): prototypes, sim, valid_num; re-zero protoAcc ----
    if (blockIdx.x == 0) {
        int t = threadIdx.x;
        int ss = t >> 5, c = t & 31;
        float a0 = g_protoAcc[0 * 256 + t];
        float a1 = g_protoAcc[1 * 256 + t];
        float a2 = g_protoAcc[2 * 256 + t];
        g_protoAcc[0 * 256 + t] = 0.f;     // restore invariant for next replay
        g_protoAcc[1 * 256 + t] = 0.f;
        g_protoAcc[2 * 256 + t] = 0.f;
        float psig = 1.0f / a0;
        float pmu = a1 / a0;
        float pw = 1.0f / a2;
        float nr2 = pmu * pmu;
#pragma unroll
        for (int ofs = 16; ofs; ofs >>= 1) nr2 += __shfl_xor_sync(0xffffffffu, nr2, ofs);
        float inv = 1.0f / fmaxf(sqrtf(nr2), 1e-12f);
        float mun = pmu * inv;
        __shared__ float sMW[8][NCH], sDen[8][NCH];
        float mw = mun * pw, den = psig * pw;
        g_posMW[ss * NCH + c] = mw;
        g_posDen[ss * NCH + c] = den;
        sMW[ss][c] = mw;
        sDen[ss][c] = den;
        __syncthreads();
        if (t < 56) {
            int i = t / 7, k = t % 7, o = (i + 1 + k) & 7;
            float sum = 0.f;
            for (int cc = 0; cc < NCH; cc++) {
                float d = sMW[i][cc] - sMW[o][cc];
                float dn = sDen[i][cc] + sDen[o][cc];
                sum += d * d / dn + logf(dn);
            }
            g_simL[i * 7 + k] = (g_count[o] > 0) ? (-sum * (1.0f / 32.0f)) : -INFF;
        }
        if (t == 0) {
            int vn = 0;
            for (int s2 = 0; s2 < 8; s2++) vn += (g_count[s2] > 0) ? 1 : 0;
            g_vnInv = (vn > 0) ? 1.0f / (float)vn : 0.f;
            out[0] = 0.f;
        }
    }
}

// ---------------- MLS logits ---------------------------------------------------------
__device__ __forceinline__ float mls_logit_h(const float* __restrict__ aMW,
                                             const float* __restrict__ aDen,
                                             const __half2* __restrict__ bpk) {
    const uint4* u = (const uint4*)bpk;   // 8 uint4, each = 4 channels of (mw,den)
    float total = 0.f;
#pragma unroll
    for (int g = 0; g < 8; g++) {
        uint4 v = u[g];
        const __half2* h = (const __half2*)&v;
        float qs = 0.f, prod = 1.f;
#pragma unroll
        for (int i = 0; i < 4; i++) {
            float2 md = __half22float2(h[i]);   // x=mw, y=den
            int c = g * 4 + i;
            float den = aDen[c] + md.y;
            float d = aMW[c] - md.x;
            qs += __fdividef(d * d, den);
            prod *= den;
        }
        total += qs + __logf(prod);
    }
    return -total * (1.0f / 32.0f);  // _mls/TEMP
}

__device__ __forceinline__ float mls_logit_f(const float* __restrict__ aMW,
                                             const float* __restrict__ aDen,
                                             const float* __restrict__ bMW,
                                             const float* __restrict__ bDen) {
    float total = 0.f;
#pragma unroll
    for (int g = 0; g < 4; g++) {
        float qs = 0.f, prod = 1.f;
#pragma unroll
        for (int i = 0; i < 8; i++) {
            int c = g * 8 + i;
            float den = aDen[c] + bDen[c];
            float d = aMW[c] - bMW[c];
            qs += __fdividef(d * d, den);
            prod *= den;
        }
        total += qs + __logf(prod);
    }
    return -total * (1.0f / 32.0f);
}

// ---------------- kernel 4: fused sampling + logits + logsumexp + CE -----------------
__global__ void __launch_bounds__(256) k_slog(float* out) {
    int i = blockIdx.x, q = blockIdx.y, t = threadIdx.x;
    int warp = t >> 5, lane = t & 31;
    __shared__ unsigned sk[4];           // k2a,k2b,k3a,k3b
    __shared__ int sap;
    __shared__ float ssim[7];
    __shared__ float aMW[NCH], aDen[NCH];
    __shared__ float sred[8];

    if (t < 7) ssim[t] = g_simL[i * 7 + t];
    if (t == 0) {
        unsigned ka, kb;
        tf2x32(0u, 42u, 0u, (unsigned)i, ka, kb);   // keys[i]
        unsigned k1a, k1b;
        tf2x32(ka, kb, 0u, 0u, k1a, k1b);           // k1
        float u = u01(rbits(k1a, k1b, (unsigned)q));
        int hc = g_hcount[i];
        int r = (int)(u * (float)hc);
        int cl = hc - 1; if (cl < 0) cl = 0;
        if (r > cl) r = cl;
        if (r < 0) r = 0;
        int ap = (hc > 0) ? g_tblH[i * NPIXT + r] : 0;
        if (ap < 0) ap = 0;
        if (ap >= NPIXT) ap = NPIXT - 1;
        sap = ap;
        unsigned a, b;
        tf2x32(ka, kb, 0u, 1u, a, b); sk[0] = a; sk[1] = b;   // k2
        tf2x32(ka, kb, 0u, 2u, a, b); sk[2] = a; sk[3] = b;   // k3
    }
    __syncthreads();
    if (t < NCH) {
        float2 md = __half22float2(g_pk[(size_t)sap * 32 + t]);
        aMW[t] = md.x;
        aDen[t] = md.y;
    }
    unsigned k2a = sk[0], k2b = sk[1], k3a = sk[2], k3b = sk[3];

    // ---- negative sampling (negative index = t) ----
    unsigned j = (unsigned)(q * 256 + t);
    unsigned b7 = j * 7u;
    float best = -INFF;
    int bi = 0;
#pragma unroll
    for (int k = 0; k < 7; k++) {
        float u = u01(rbits(k2a, k2b, b7 + k));
        u = fmaxf(u + TINYF, TINYF);
        float g = -__logf(-__logf(u));
        float v = g + ssim[k];
        if (v > best) { best = v; bi = k; }
    }
    int cls = (i + 1 + bi) & 7;
    int cnt = g_count[cls];
    float u3 = u01(rbits(k3a, k3b, j));
    int r = (int)(u3 * (float)cnt);
    int cl = cnt - 1; if (cl < 0) cl = 0;
    if (r > cl) r = cl;
    if (r < 0) r = 0;
    int p = g_tblV[cls * NPIXT + r];
    if (p < 0) p = 0;
    if (p >= NPIXT) p = NPIXT - 1;
    __syncthreads();   // anchor smem ready

    // ---- logits: lg0 = this thread's NEGATIVE, lg1 (t==0 only) = POSITIVE ----
    float lg0 = mls_logit_h(aMW, aDen, g_pk + (size_t)p * 32);
    float lg1 = (t == 0) ? mls_logit_f(aMW, aDen, g_posMW + i * NCH, g_posDen + i * NCH)
                         : -INFF;

    // ---- block logsumexp ----
    float mymax = fmaxf(lg0, lg1);
#pragma unroll
    for (int ofs = 16; ofs; ofs >>= 1) mymax = fmaxf(mymax, __shfl_xor_sync(0xffffffffu, mymax, ofs));
    if (lane == 0) sred[warp] = mymax;
    __syncthreads();
    if (t == 0) {
        float m = sred[0];
#pragma unroll
        for (int w2 = 1; w2 < 8; w2++) m = fmaxf(m, sred[w2]);
        sred[0] = m;
    }
    __syncthreads();
    float M = sred[0];
    __syncthreads();
    float ex = __expf(lg0 - M) + ((t == 0) ? __expf(lg1 - M) : 0.f);
#pragma unroll
    for (int ofs = 16; ofs; ofs >>= 1) ex += __shfl_xor_sync(0xffffffffu, ex, ofs);
    if (lane == 0) sred[warp] = ex;
    __syncthreads();
    if (t == 0) {
        float sum = 0.f;
#pragma unroll
        for (int w2 = 0; w2 < 8; w2++) sum += sred[w2];
        float lse = M + __logf(sum);
        bool ok = (g_hcount[i] > 0) && (g_count[i] > 0);
        if (ok) atomicAdd(out, (lse - lg1) * g_vnInv * (1.0f / 256.0f));
    }
}

// ---------------- launch ----------------
extern "C" void kernel_launch(void* const* d_in, const int* in_sizes, int n_in,
                              void* d_out, int out_size) {
    const float* weights = (const float*)d_in[0];
    const float* mu      = (const float*)d_in[1];
    const float* sigma   = (const float*)d_in[2];
    const float* label   = (const float*)d_in[3];
    const float* mask    = (const float*)d_in[4];
    const float* prob    = (const float*)d_in[5];
    float* out = (float*)d_out;

    k_main<<<NBLK, 256>>>(weights, mu, sigma, label, mask, prob);
    k_scan<<<16, NBLK>>>();
    k_scatter<<<NBLK, 256>>>(out);
    k_slog<<<dim3(8, 256), 256>>>(out);
}